// round 2
// baseline (speedup 1.0000x reference)
#include <cuda_runtime.h>
#include <cstdint>

// ScaledDotProductAttention: B=2,H=16,S=2048,D=64, causal, fp32 in/out.
// FlashAttention-2 style, tf32 mma.sync (m16n8k8), online softmax,
// causal tile skipping. Inputs: d_in[0]=q, d_in[1]=k, d_in[2]=v,
// d_in[3]=causal_mask (ignored; mask is exactly tril).

#define S_LEN 2048
#define DH 64
#define BM 64
#define BN 64
#define B_SZ 2
#define H_SZ 16
#define LOG2E 1.4426950408889634f

__device__ __forceinline__ uint32_t f2tf32(float f) {
    uint32_t u;
    asm("cvt.rna.tf32.f32 %0, %1;" : "=r"(u) : "f"(f));
    return u;
}

__device__ __forceinline__ void mma_tf32(float c[4],
                                         uint32_t a0, uint32_t a1, uint32_t a2, uint32_t a3,
                                         uint32_t b0, uint32_t b1) {
    asm volatile(
        "mma.sync.aligned.m16n8k8.row.col.f32.tf32.tf32.f32 "
        "{%0,%1,%2,%3}, {%4,%5,%6,%7}, {%8,%9}, {%0,%1,%2,%3};"
        : "+f"(c[0]), "+f"(c[1]), "+f"(c[2]), "+f"(c[3])
        : "r"(a0), "r"(a1), "r"(a2), "r"(a3), "r"(b0), "r"(b1));
}

__global__ void __launch_bounds__(128)
fa_tf32_kernel(const float* __restrict__ Q, const float* __restrict__ K,
               const float* __restrict__ V, float* __restrict__ O)
{
    // Padded strides chosen for conflict-free b-fragment loads:
    //   sK stride 68: bank = 4g + t  (32 distinct lanes)
    //   sV stride 72: bank = 8t + g  (32 distinct lanes)
    __shared__ uint32_t sK[BN][68];
    __shared__ uint32_t sV[BN][72];

    const int qt   = blockIdx.x;            // q tile: rows [qt*64, qt*64+64)
    const int bh   = blockIdx.y;            // b*H + h
    const int tid  = threadIdx.x;
    const int wid  = tid >> 5;
    const int lane = tid & 31;
    const int g    = lane >> 2;             // 0..7
    const int t    = lane & 3;              // 0..3

    const size_t base = (size_t)bh * S_LEN * DH;
    const float* Qb = Q + base;
    const float* Kb = K + base;
    const float* Vb = V + base;
    float*       Ob = O + base;

    const int q0   = qt * BM;
    const int row0 = q0 + wid * 16 + g;     // this thread's rows: row0, row0+8

    // --- Q fragments (A of QK^T), pre-scaled by log2(e)/sqrt(D), tf32 ---
    uint32_t aQ[8][4];
    const float qscale = LOG2E * 0.125f;    // 1/sqrt(64) = 1/8
    #pragma unroll
    for (int k8 = 0; k8 < 8; k8++) {
        aQ[k8][0] = f2tf32(Qb[(size_t)(row0)     * DH + 8*k8 + t    ] * qscale);
        aQ[k8][1] = f2tf32(Qb[(size_t)(row0 + 8) * DH + 8*k8 + t    ] * qscale);
        aQ[k8][2] = f2tf32(Qb[(size_t)(row0)     * DH + 8*k8 + t + 4] * qscale);
        aQ[k8][3] = f2tf32(Qb[(size_t)(row0 + 8) * DH + 8*k8 + t + 4] * qscale);
    }

    // Output accumulators + online softmax state
    float o[8][4];
    #pragma unroll
    for (int n = 0; n < 8; n++)
        o[n][0] = o[n][1] = o[n][2] = o[n][3] = 0.f;
    float m0 = -INFINITY, m1 = -INFINITY;
    float l0 = 0.f, l1 = 0.f;

    // Shuffle sources for P(C-layout) -> A-fragment re-layout
    const int srcA = (lane & 28) | (t >> 1);
    const int srcB = srcA + 2;
    const bool odd = (t & 1);

    for (int kt = 0; kt <= qt; kt++) {
        const int k0 = kt * BN;

        // --- stage K,V tile into smem, converted to tf32 ---
        #pragma unroll
        for (int i = 0; i < 8; i++) {
            int lin = (i << 7) + tid;       // 0..1023
            int r   = lin >> 4;             // 0..63
            int c4  = (lin & 15) << 2;      // 0..60
            const float4 kf = *reinterpret_cast<const float4*>(&Kb[(size_t)(k0 + r) * DH + c4]);
            const float4 vf = *reinterpret_cast<const float4*>(&Vb[(size_t)(k0 + r) * DH + c4]);
            uint4 ku = make_uint4(f2tf32(kf.x), f2tf32(kf.y), f2tf32(kf.z), f2tf32(kf.w));
            uint4 vu = make_uint4(f2tf32(vf.x), f2tf32(vf.y), f2tf32(vf.z), f2tf32(vf.w));
            *reinterpret_cast<uint4*>(&sK[r][c4]) = ku;
            *reinterpret_cast<uint4*>(&sV[r][c4]) = vu;
        }
        __syncthreads();

        // --- S = Q * K^T (scaled, log2 domain) ---
        float c[8][4];
        #pragma unroll
        for (int n = 0; n < 8; n++) {
            c[n][0] = c[n][1] = c[n][2] = c[n][3] = 0.f;
            #pragma unroll
            for (int k8 = 0; k8 < 8; k8++) {
                uint32_t b0 = sK[8*n + g][8*k8 + t];
                uint32_t b1 = sK[8*n + g][8*k8 + t + 4];
                mma_tf32(c[n], aQ[k8][0], aQ[k8][1], aQ[k8][2], aQ[k8][3], b0, b1);
            }
        }

        // --- causal mask (diagonal tile only) ---
        if (kt == qt) {
            #pragma unroll
            for (int n = 0; n < 8; n++) {
                int j0 = k0 + 8*n + 2*t;
                if (j0     > row0)     c[n][0] = -1e30f;
                if (j0 + 1 > row0)     c[n][1] = -1e30f;
                if (j0     > row0 + 8) c[n][2] = -1e30f;
                if (j0 + 1 > row0 + 8) c[n][3] = -1e30f;
            }
        }

        // --- row max (per-thread, then quad shuffle reduce) ---
        float tm0 = -INFINITY, tm1 = -INFINITY;
        #pragma unroll
        for (int n = 0; n < 8; n++) {
            tm0 = fmaxf(tm0, fmaxf(c[n][0], c[n][1]));
            tm1 = fmaxf(tm1, fmaxf(c[n][2], c[n][3]));
        }
        tm0 = fmaxf(tm0, __shfl_xor_sync(0xffffffffu, tm0, 1));
        tm0 = fmaxf(tm0, __shfl_xor_sync(0xffffffffu, tm0, 2));
        tm1 = fmaxf(tm1, __shfl_xor_sync(0xffffffffu, tm1, 1));
        tm1 = fmaxf(tm1, __shfl_xor_sync(0xffffffffu, tm1, 2));

        const float mn0 = fmaxf(m0, tm0);
        const float mn1 = fmaxf(m1, tm1);
        const float al0 = exp2f(m0 - mn0);
        const float al1 = exp2f(m1 - mn1);

        // --- P = exp2(S - m), accumulate row sums, convert P to tf32 in-place ---
        float sp0 = 0.f, sp1 = 0.f;
        #pragma unroll
        for (int n = 0; n < 8; n++) {
            float p0 = exp2f(c[n][0] - mn0);
            float p1 = exp2f(c[n][1] - mn0);
            float p2 = exp2f(c[n][2] - mn1);
            float p3 = exp2f(c[n][3] - mn1);
            sp0 += p0 + p1;
            sp1 += p2 + p3;
            c[n][0] = __uint_as_float(f2tf32(p0));
            c[n][1] = __uint_as_float(f2tf32(p1));
            c[n][2] = __uint_as_float(f2tf32(p2));
            c[n][3] = __uint_as_float(f2tf32(p3));
        }
        sp0 += __shfl_xor_sync(0xffffffffu, sp0, 1);
        sp0 += __shfl_xor_sync(0xffffffffu, sp0, 2);
        sp1 += __shfl_xor_sync(0xffffffffu, sp1, 1);
        sp1 += __shfl_xor_sync(0xffffffffu, sp1, 2);

        l0 = l0 * al0 + sp0;
        l1 = l1 * al1 + sp1;
        m0 = mn0;
        m1 = mn1;

        #pragma unroll
        for (int n = 0; n < 8; n++) {
            o[n][0] *= al0; o[n][1] *= al0;
            o[n][2] *= al1; o[n][3] *= al1;
        }

        // --- O += P * V ---
        #pragma unroll
        for (int kk = 0; kk < 8; kk++) {
            // Re-layout P (C frag of tile kk) into A frag via shuffles.
            float x0 = __shfl_sync(0xffffffffu, c[kk][0], srcA);
            float x1 = __shfl_sync(0xffffffffu, c[kk][1], srcA);
            float y0 = __shfl_sync(0xffffffffu, c[kk][0], srcB);
            float y1 = __shfl_sync(0xffffffffu, c[kk][1], srcB);
            float z0 = __shfl_sync(0xffffffffu, c[kk][2], srcA);
            float z1 = __shfl_sync(0xffffffffu, c[kk][3], srcA);
            float w0 = __shfl_sync(0xffffffffu, c[kk][2], srcB);
            float w1 = __shfl_sync(0xffffffffu, c[kk][3], srcB);
            uint32_t a0 = __float_as_uint(odd ? x1 : x0);
            uint32_t a1 = __float_as_uint(odd ? z1 : z0);
            uint32_t a2 = __float_as_uint(odd ? y1 : y0);
            uint32_t a3 = __float_as_uint(odd ? w1 : w0);
            #pragma unroll
            for (int n = 0; n < 8; n++) {
                uint32_t b0 = sV[8*kk + t    ][8*n + g];
                uint32_t b1 = sV[8*kk + t + 4][8*n + g];
                mma_tf32(o[n], a0, a1, a2, a3, b0, b1);
            }
        }
        __syncthreads();
    }

    // --- epilogue: normalize and store ---
    const float il0 = 1.0f / l0;
    const float il1 = 1.0f / l1;
    #pragma unroll
    for (int n = 0; n < 8; n++) {
        float2 r0v = make_float2(o[n][0] * il0, o[n][1] * il0);
        float2 r1v = make_float2(o[n][2] * il1, o[n][3] * il1);
        *reinterpret_cast<float2*>(&Ob[(size_t)(row0)     * DH + 8*n + 2*t]) = r0v;
        *reinterpret_cast<float2*>(&Ob[(size_t)(row0 + 8) * DH + 8*n + 2*t]) = r1v;
    }
}

extern "C" void kernel_launch(void* const* d_in, const int* in_sizes, int n_in,
                              void* d_out, int out_size) {
    const float* q = (const float*)d_in[0];
    const float* k = (const float*)d_in[1];
    const float* v = (const float*)d_in[2];
    // d_in[3] = causal_mask: exactly lower-triangular, handled analytically.
    float* o = (float*)d_out;

    dim3 grid(S_LEN / BM, B_SZ * H_SZ);   // (32, 32)
    fa_tf32_kernel<<<grid, 128>>>(q, k, v, o);
}